// round 2
// baseline (speedup 1.0000x reference)
#include <cuda_runtime.h>
#include <cstdint>

#define L  2
#define T  128
#define NB 64      // batch N
#define H  512
#define E  256
#define A  200
#define V  1000
#define S  40
#define LT (L*T)   // 256

// ---------------- scratch (device globals; no allocation allowed) ----------------
__device__ float g_Kproj[L*T*NB*A];    // (l,t,n,a)
__device__ float g_QwT[L*H*A];         // (l,k,a)
__device__ float g_qproj[L*NB*A];      // (l,n,a)
__device__ float g_scores[NB*LT];      // (n, lt)
__device__ float g_x[(E+H)*NB];        // (k,n) transposed GRU0 input
__device__ float g_h[2][L][H*NB];      // [pingpong][layer][(k,n)]
__device__ float g_proj[H*NB];         // (k,n)

// ---------------- MUFU-free fast math ----------------
__device__ __forceinline__ float fast_rcp(float q) {
    // q > 0 here. Bit-trick seed + 3 Newton steps (pure FMA/ALU, no MUFU).
    float r = __uint_as_float(0x7EF311C3u - __float_as_uint(q));
    r = r * (2.0f - q * r);
    r = r * (2.0f - q * r);
    r = r * (2.0f - q * r);
    return r;
}

__device__ __forceinline__ float tanh_fast(float x) {
    // Eigen ptanh_float rational approx, division replaced by fast_rcp.
    const float c = 7.99881172180175781f;
    x = fminf(fmaxf(x, -c), c);
    float x2 = x * x;
    float p = fmaf(x2, -2.76076847742355e-16f, 2.00018790482477e-13f);
    p = fmaf(x2, p, -8.60467152213735e-11f);
    p = fmaf(x2, p,  5.12229709037114e-08f);
    p = fmaf(x2, p,  1.48572235717979e-05f);
    p = fmaf(x2, p,  6.37261928875436e-04f);
    p = fmaf(x2, p,  4.89352455891786e-03f);
    p = p * x;
    float q = fmaf(x2, 1.19825839466702e-06f, 1.18534705686654e-04f);
    q = fmaf(x2, q, 2.26843463243900e-03f);
    q = fmaf(x2, q, 4.89352518554385e-03f);
    return p * fast_rcp(q);
}

__device__ __forceinline__ float sigmoid_fast(float x) {
    return fmaf(tanh_fast(0.5f * x), 0.5f, 0.5f);
}

// ---------------- prep kernels (run once per launch) ----------------
__global__ void prep_qwt(const float* __restrict__ Qw) {
    int i = blockIdx.x * 256 + threadIdx.x;        // over L*A*H
    if (i >= L * A * H) return;
    int k = i % H;
    int a = (i / H) % A;
    int l = i / (A * H);
    g_QwT[(l * H + k) * A + a] = Qw[i];
}

__global__ void prep_hinit(const float* __restrict__ efs) {
    int i = blockIdx.x * 256 + threadIdx.x;        // over L*NB*H
    if (i >= L * NB * H) return;
    int k = i % H;
    int n = (i / H) % NB;
    int l = i / (NB * H);
    g_h[0][l][k * NB + n] = efs[i];
}

// Kproj[l,tn,a] = sum_h eo[l,tn,h] * Kw[l,a,h] + Kb[l,a]
// Tiled SGEMM: BM=64(tn) x BN=64(a) x BK=16, 256 threads, 4x4 per thread.
__global__ void kproj_gemm(const float* __restrict__ eo,
                           const float* __restrict__ Kw,
                           const float* __restrict__ Kb) {
    const int l   = blockIdx.z;
    const int tn0 = blockIdx.x * 64;
    const int a0  = blockIdx.y * 64;
    const float* Ab = eo + (size_t)l * (T * NB) * H;   // [8192,512]
    const float* Bb = Kw + (size_t)l * A * H;          // [200,512]
    __shared__ float As[16][64];
    __shared__ float Bs[16][64];
    const int tid = threadIdx.x;
    const int tr = tid >> 4, tc = tid & 15;
    const int lr = tid >> 2;             // 0..63
    const int lk = (tid & 3) * 4;        // 0,4,8,12
    float acc[4][4];
    #pragma unroll
    for (int i = 0; i < 4; i++)
        #pragma unroll
        for (int j = 0; j < 4; j++) acc[i][j] = 0.0f;

    for (int k0 = 0; k0 < H; k0 += 16) {
        float4 a4 = *reinterpret_cast<const float4*>(&Ab[(size_t)(tn0 + lr) * H + k0 + lk]);
        As[lk + 0][lr] = a4.x; As[lk + 1][lr] = a4.y;
        As[lk + 2][lr] = a4.z; As[lk + 3][lr] = a4.w;
        float4 b4 = make_float4(0.f, 0.f, 0.f, 0.f);
        if (a0 + lr < A)
            b4 = *reinterpret_cast<const float4*>(&Bb[(size_t)(a0 + lr) * H + k0 + lk]);
        Bs[lk + 0][lr] = b4.x; Bs[lk + 1][lr] = b4.y;
        Bs[lk + 2][lr] = b4.z; Bs[lk + 3][lr] = b4.w;
        __syncthreads();
        #pragma unroll
        for (int kk = 0; kk < 16; kk++) {
            float4 av = *reinterpret_cast<const float4*>(&As[kk][tr * 4]);
            float4 bv = *reinterpret_cast<const float4*>(&Bs[kk][tc * 4]);
            acc[0][0] = fmaf(av.x, bv.x, acc[0][0]);
            acc[0][1] = fmaf(av.x, bv.y, acc[0][1]);
            acc[0][2] = fmaf(av.x, bv.z, acc[0][2]);
            acc[0][3] = fmaf(av.x, bv.w, acc[0][3]);
            acc[1][0] = fmaf(av.y, bv.x, acc[1][0]);
            acc[1][1] = fmaf(av.y, bv.y, acc[1][1]);
            acc[1][2] = fmaf(av.y, bv.z, acc[1][2]);
            acc[1][3] = fmaf(av.y, bv.w, acc[1][3]);
            acc[2][0] = fmaf(av.z, bv.x, acc[2][0]);
            acc[2][1] = fmaf(av.z, bv.y, acc[2][1]);
            acc[2][2] = fmaf(av.z, bv.z, acc[2][2]);
            acc[2][3] = fmaf(av.z, bv.w, acc[2][3]);
            acc[3][0] = fmaf(av.w, bv.x, acc[3][0]);
            acc[3][1] = fmaf(av.w, bv.y, acc[3][1]);
            acc[3][2] = fmaf(av.w, bv.z, acc[3][2]);
            acc[3][3] = fmaf(av.w, bv.w, acc[3][3]);
        }
        __syncthreads();
    }
    #pragma unroll
    for (int i = 0; i < 4; i++) {
        int tn = tn0 + tr * 4 + i;
        #pragma unroll
        for (int j = 0; j < 4; j++) {
            int a = a0 + tc * 4 + j;
            if (a < A)
                g_Kproj[(size_t)(l * T * NB + tn) * A + a] = acc[i][j] + Kb[l * A + a];
        }
    }
}

// ---------------- per-step kernels ----------------

// qproj[l,n,a] = sum_k h[l,k,n] * QwT[l,k,a] + Qb[l,a]
// grid (16, L), 256 threads; block handles l, 4 consecutive n; thread = a.
__global__ void qproj_kernel(const float* __restrict__ Qb, int cur) {
    int l = blockIdx.y;
    int n0 = blockIdx.x * 4;
    int a = threadIdx.x;
    if (a >= A) return;
    const float* hp = g_h[cur][l];
    const float* qw = g_QwT + (size_t)l * H * A + a;
    float a0 = 0.f, a1 = 0.f, a2 = 0.f, a3 = 0.f;
    #pragma unroll 4
    for (int k = 0; k < H; k++) {
        float w = qw[(size_t)k * A];
        float h0 = hp[k * NB + n0 + 0];
        float h1 = hp[k * NB + n0 + 1];
        float h2 = hp[k * NB + n0 + 2];
        float h3 = hp[k * NB + n0 + 3];
        a0 = fmaf(w, h0, a0);
        a1 = fmaf(w, h1, a1);
        a2 = fmaf(w, h2, a2);
        a3 = fmaf(w, h3, a3);
    }
    float b = Qb[l * A + a];
    g_qproj[(l * NB + n0 + 0) * A + a] = a0 + b;
    g_qproj[(l * NB + n0 + 1) * A + a] = a1 + b;
    g_qproj[(l * NB + n0 + 2) * A + a] = a2 + b;
    g_qproj[(l * NB + n0 + 3) * A + a] = a3 + b;
}

// scores[n, lt] = sum_a Vw[l,a]*tanh(qproj[l,n,a] + Kproj[l,t,n,a]) + Vb[l]
// grid (T, L), 256 threads = 8 warps; warp handles rows n = warp + 8*i.
__global__ void scores_kernel(const float* __restrict__ Vw,
                              const float* __restrict__ Vb) {
    int t = blockIdx.x, l = blockIdx.y;
    int warp = threadIdx.x >> 5, lane = threadIdx.x & 31;
    int lt = l * T + t;
    const float* vw = Vw + l * A;
    float vb = Vb[l];
    for (int n = warp; n < NB; n += 8) {
        const float* kp = g_Kproj + (size_t)(lt * NB + n) * A;
        const float* qp = g_qproj + (size_t)(l * NB + n) * A;
        float acc = 0.f;
        for (int a = lane; a < A; a += 32)
            acc = fmaf(vw[a], tanh_fast(qp[a] + kp[a]), acc);
        #pragma unroll
        for (int o = 16; o > 0; o >>= 1)
            acc += __shfl_down_sync(0xFFFFFFFFu, acc, o);
        if (lane == 0) g_scores[n * LT + lt] = acc + vb;
    }
}

// Softmax over lt (256) per n, context accumulation, plus embedding -> g_x (k,n).
// grid (4 hchunks, NB), 128 threads.
__global__ void context_kernel(const float* __restrict__ eo,
                               const float* __restrict__ embW,
                               const int* __restrict__ targets, int s) {
    __shared__ float w[LT];
    __shared__ float red[128];
    int n = blockIdx.y;
    int hc = blockIdx.x;
    int tid = threadIdx.x;

    float s0 = g_scores[n * LT + tid];
    float s1 = g_scores[n * LT + tid + 128];
    red[tid] = fmaxf(s0, s1);
    __syncthreads();
    #pragma unroll
    for (int o = 64; o > 0; o >>= 1) {
        if (tid < o) red[tid] = fmaxf(red[tid], red[tid + o]);
        __syncthreads();
    }
    float mx = red[0];
    __syncthreads();
    float e0 = __expf(s0 - mx), e1 = __expf(s1 - mx);
    red[tid] = e0 + e1;
    __syncthreads();
    #pragma unroll
    for (int o = 64; o > 0; o >>= 1) {
        if (tid < o) red[tid] += red[tid + o];
        __syncthreads();
    }
    float inv = 1.0f / red[0];
    w[tid] = e0 * inv;
    w[tid + 128] = e1 * inv;
    __syncthreads();

    int h = hc * 128 + tid;
    const float* eop = eo + (size_t)n * H + h;     // stride NB*H between lt
    float acc = 0.f;
    #pragma unroll 4
    for (int lt = 0; lt < LT; lt++)
        acc = fmaf(w[lt], eop[(size_t)lt * (NB * H)], acc);
    g_x[(E + h) * NB + n] = acc;

    if (hc == 0) {
        int tok = (s == 0) ? 1 : targets[n * S + (s - 1)];
        for (int e = tid; e < E; e += 128)
            g_x[e * NB + n] = fmaxf(embW[tok * E + e], 0.0f);
    }
}

// GRU cell: thread = (n, j). grid 128 blocks, blockDim (64,4).
// layer==0: input g_x (KIN=768); layer==1: input g_h[nxt][0] (KIN=512).
template <int KIN>
__global__ void gru_kernel(const float* __restrict__ Wih,
                           const float* __restrict__ Whh,
                           const float* __restrict__ bih,
                           const float* __restrict__ bhh,
                           int cur, int nxt, int layer) {
    int n = threadIdx.x;
    int j = blockIdx.x * blockDim.y + threadIdx.y;
    const float* x = (layer == 0) ? g_x : g_h[nxt][0];
    const float* hsrc = g_h[cur][layer];
    float* hdst = g_h[nxt][layer];

    const float* wr = Wih + (size_t)j * KIN;
    const float* wz = Wih + (size_t)(H + j) * KIN;
    const float* wn = Wih + (size_t)(2 * H + j) * KIN;
    float ir = 0.f, iz = 0.f, in_ = 0.f;
    #pragma unroll 4
    for (int k = 0; k < KIN; k += 4) {
        float4 r4 = *reinterpret_cast<const float4*>(wr + k);
        float4 z4 = *reinterpret_cast<const float4*>(wz + k);
        float4 n4 = *reinterpret_cast<const float4*>(wn + k);
        float x0 = x[(k + 0) * NB + n];
        float x1 = x[(k + 1) * NB + n];
        float x2 = x[(k + 2) * NB + n];
        float x3 = x[(k + 3) * NB + n];
        ir = fmaf(x0, r4.x, ir); ir = fmaf(x1, r4.y, ir);
        ir = fmaf(x2, r4.z, ir); ir = fmaf(x3, r4.w, ir);
        iz = fmaf(x0, z4.x, iz); iz = fmaf(x1, z4.y, iz);
        iz = fmaf(x2, z4.z, iz); iz = fmaf(x3, z4.w, iz);
        in_ = fmaf(x0, n4.x, in_); in_ = fmaf(x1, n4.y, in_);
        in_ = fmaf(x2, n4.z, in_); in_ = fmaf(x3, n4.w, in_);
    }
    const float* vr = Whh + (size_t)j * H;
    const float* vz = Whh + (size_t)(H + j) * H;
    const float* vn = Whh + (size_t)(2 * H + j) * H;
    float hr = 0.f, hz = 0.f, hn = 0.f;
    #pragma unroll 4
    for (int k = 0; k < H; k += 4) {
        float4 r4 = *reinterpret_cast<const float4*>(vr + k);
        float4 z4 = *reinterpret_cast<const float4*>(vz + k);
        float4 n4 = *reinterpret_cast<const float4*>(vn + k);
        float h0 = hsrc[(k + 0) * NB + n];
        float h1 = hsrc[(k + 1) * NB + n];
        float h2 = hsrc[(k + 2) * NB + n];
        float h3 = hsrc[(k + 3) * NB + n];
        hr = fmaf(h0, r4.x, hr); hr = fmaf(h1, r4.y, hr);
        hr = fmaf(h2, r4.z, hr); hr = fmaf(h3, r4.w, hr);
        hz = fmaf(h0, z4.x, hz); hz = fmaf(h1, z4.y, hz);
        hz = fmaf(h2, z4.z, hz); hz = fmaf(h3, z4.w, hz);
        hn = fmaf(h0, n4.x, hn); hn = fmaf(h1, n4.y, hn);
        hn = fmaf(h2, n4.z, hn); hn = fmaf(h3, n4.w, hn);
    }
    float r = sigmoid_fast(ir + bih[j] + hr + bhh[j]);
    float z = sigmoid_fast(iz + bih[H + j] + hz + bhh[H + j]);
    float nn = tanh_fast(in_ + bih[2 * H + j] + r * (hn + bhh[2 * H + j]));
    float hprev = hsrc[j * NB + n];
    hdst[j * NB + n] = fmaf(z, hprev - nn, nn);   // (1-z)*nn + z*hprev
}

// proj[j,n] = relu(sum_k h1[k,n]*Pw0[j,k] + Pb0[j]); grid 128, blockDim (64,4)
__global__ void proj_kernel(const float* __restrict__ Pw0,
                            const float* __restrict__ Pb0, int nxt) {
    int n = threadIdx.x;
    int j = blockIdx.x * blockDim.y + threadIdx.y;
    const float* h1 = g_h[nxt][1];
    const float* wrow = Pw0 + (size_t)j * H;
    float acc = 0.f;
    #pragma unroll 4
    for (int k = 0; k < H; k += 4) {
        float4 w4 = *reinterpret_cast<const float4*>(wrow + k);
        acc = fmaf(h1[(k + 0) * NB + n], w4.x, acc);
        acc = fmaf(h1[(k + 1) * NB + n], w4.y, acc);
        acc = fmaf(h1[(k + 2) * NB + n], w4.z, acc);
        acc = fmaf(h1[(k + 3) * NB + n], w4.w, acc);
    }
    g_proj[j * NB + n] = fmaxf(acc + Pb0[j], 0.0f);
}

// logits: out[n,s,v] = sum_k proj[k,n]*Pw1[v,k] + Pb1[v]; grid 250, blockDim (64,4)
__global__ void logits_kernel(const float* __restrict__ Pw1,
                              const float* __restrict__ Pb1,
                              float* __restrict__ out, int s) {
    int n = threadIdx.x;
    int v = blockIdx.x * blockDim.y + threadIdx.y;
    if (v >= V) return;
    const float* wrow = Pw1 + (size_t)v * H;
    float acc = 0.f;
    #pragma unroll 4
    for (int k = 0; k < H; k += 4) {
        float4 w4 = *reinterpret_cast<const float4*>(wrow + k);
        acc = fmaf(g_proj[(k + 0) * NB + n], w4.x, acc);
        acc = fmaf(g_proj[(k + 1) * NB + n], w4.y, acc);
        acc = fmaf(g_proj[(k + 2) * NB + n], w4.z, acc);
        acc = fmaf(g_proj[(k + 3) * NB + n], w4.w, acc);
    }
    out[((size_t)n * S + s) * V + v] = acc + Pb1[v];
}

// ---------------- launcher ----------------
extern "C" void kernel_launch(void* const* d_in, const int* in_sizes, int n_in,
                              void* d_out, int out_size) {
    const float* eo      = (const float*)d_in[0];
    const float* efs     = (const float*)d_in[1];
    const int*   targets = (const int*)  d_in[2];
    const float* embW    = (const float*)d_in[3];
    const float* Qw      = (const float*)d_in[4];
    const float* Qb      = (const float*)d_in[5];
    const float* Kw      = (const float*)d_in[6];
    const float* Kb      = (const float*)d_in[7];
    const float* Vw      = (const float*)d_in[8];
    const float* Vb      = (const float*)d_in[9];
    const float* Wih0    = (const float*)d_in[10];
    const float* Whh0    = (const float*)d_in[11];
    const float* bih0    = (const float*)d_in[12];
    const float* bhh0    = (const float*)d_in[13];
    const float* Wih1    = (const float*)d_in[14];
    const float* Whh1    = (const float*)d_in[15];
    const float* bih1    = (const float*)d_in[16];
    const float* bhh1    = (const float*)d_in[17];
    const float* Pw0     = (const float*)d_in[18];
    const float* Pb0     = (const float*)d_in[19];
    const float* Pw1     = (const float*)d_in[20];
    const float* Pb1     = (const float*)d_in[21];
    float* out = (float*)d_out;

    prep_qwt<<<(L * A * H + 255) / 256, 256>>>(Qw);
    prep_hinit<<<(L * NB * H + 255) / 256, 256>>>(efs);
    kproj_gemm<<<dim3(128, 4, 2), 256>>>(eo, Kw, Kb);

    dim3 blk64x4(64, 4);
    for (int s = 0; s < S; s++) {
        int cur = s & 1;
        int nxt = cur ^ 1;
        qproj_kernel<<<dim3(16, L), 256>>>(Qb, cur);
        scores_kernel<<<dim3(T, L), 256>>>(Vw, Vb);
        context_kernel<<<dim3(4, NB), 128>>>(eo, embW, targets, s);
        gru_kernel<E + H><<<128, blk64x4>>>(Wih0, Whh0, bih0, bhh0, cur, nxt, 0);
        gru_kernel<H><<<128, blk64x4>>>(Wih1, Whh1, bih1, bhh1, cur, nxt, 1);
        proj_kernel<<<128, blk64x4>>>(Pw0, Pb0, nxt);
        logits_kernel<<<250, blk64x4>>>(Pw1, Pb1, out, s);
    }
}